// round 5
// baseline (speedup 1.0000x reference)
#include <cuda_runtime.h>
#include <cuda_bf16.h>
#include <cstdint>

// ============================================================================
// BiBoSparseMoeBlock: top-2-of-8 MoE SwiGLU, fp32 in/out.
// Round 5: mma.sync bf16 hi/lo split (3 MMAs). Wider CTA tiles (N=64/128),
// 2-stage pipeline, 2 CTAs/SM, conflict-free row-per-thread cp.async loader.
// ============================================================================

#define HID   2048
#define INTER 1024
#define NEXP  8
#define MAXT  4096
#define MAXSLOTS (2 * MAXT)

typedef unsigned int u32;

// ---- device scratch ---------------------------------------------------------
__device__ int   g_cnt[NEXP];
__device__ int   g_off[NEXP];
__device__ int   g_fill[NEXP];
__device__ int   g_perm[MAXSLOTS];
__device__ float g_w[MAXSLOTS];
__device__ int   g_tidx[MAXT * 2];
__device__ float g_tw[MAXT * 2];
__device__ int   g_slot_of[MAXT * 2];

__device__ __nv_bfloat16 g_Xh[(size_t)MAXT * HID];
__device__ __nv_bfloat16 g_Xl[(size_t)MAXT * HID];
__device__ __nv_bfloat16 g_Wgh[(size_t)NEXP * INTER * HID];
__device__ __nv_bfloat16 g_Wgl[(size_t)NEXP * INTER * HID];
__device__ __nv_bfloat16 g_Wuh[(size_t)NEXP * INTER * HID];
__device__ __nv_bfloat16 g_Wul[(size_t)NEXP * INTER * HID];
__device__ __nv_bfloat16 g_Wdh[(size_t)NEXP * HID * INTER];
__device__ __nv_bfloat16 g_Wdl[(size_t)NEXP * HID * INTER];
__device__ __nv_bfloat16 g_Hh[(size_t)MAXSLOTS * INTER];
__device__ __nv_bfloat16 g_Hl[(size_t)MAXSLOTS * INTER];
__device__ float g_y[(size_t)MAXSLOTS * HID];

// ---- PTX helpers (baseline sm_80-era only) -------------------------------------
__device__ __forceinline__ u32 smem_u32(const void* p) {
    u32 a;
    asm("{ .reg .u64 t; cvta.to.shared.u64 t, %1; cvt.u32.u64 %0, t; }" : "=r"(a) : "l"(p));
    return a;
}
__device__ __forceinline__ void cpa16(u32 dst, const void* src) {
    asm volatile("cp.async.cg.shared.global [%0], [%1], 16;" :: "r"(dst), "l"(src));
}
#define CPA_COMMIT() asm volatile("cp.async.commit_group;" ::: "memory")
#define CPA_WAIT0()  asm volatile("cp.async.wait_group 0;" ::: "memory")

__device__ __forceinline__ void ldsm4(u32* r, u32 addr) {
    asm volatile("ldmatrix.sync.aligned.m8n8.x4.shared.b16 {%0,%1,%2,%3}, [%4];"
                 : "=r"(r[0]), "=r"(r[1]), "=r"(r[2]), "=r"(r[3]) : "r"(addr));
}
__device__ __forceinline__ void mma16816(float* c, const u32* a, u32 b0, u32 b1) {
    asm volatile(
        "mma.sync.aligned.m16n8k16.row.col.f32.bf16.bf16.f32 "
        "{%0,%1,%2,%3}, {%4,%5,%6,%7}, {%8,%9}, {%0,%1,%2,%3};"
        : "+f"(c[0]), "+f"(c[1]), "+f"(c[2]), "+f"(c[3])
        : "r"(a[0]), "r"(a[1]), "r"(a[2]), "r"(a[3]), "r"(b0), "r"(b1));
}

// ---- smem geometry: BK=32 bf16 rows (64B data), pitch 80B ----------------------
// ldmatrix 8-row groups: bank group (5r + c) mod 8 is a permutation -> clean.
// Loader: one warp = 32 distinct rows at same chunk -> perfectly balanced banks.
#define PITCH 80
#define OFF_AH 0
#define OFF_AL 10240          // 128 rows * 80
#define OFF_BH 20480
#define OFF_BL 30720
#define STAGE_BYTES 40960
#define NSTAGE 2
#define SMEM_DYN (NSTAGE * STAGE_BYTES)   // 81920

// ---- small kernels --------------------------------------------------------------
__global__ void zero_counters_kernel() {
    int i = threadIdx.x;
    if (i < NEXP) { g_cnt[i] = 0; g_fill[i] = 0; }
}

__global__ void router_kernel(const float* __restrict__ x,
                              const float* __restrict__ Wr,
                              float* __restrict__ logits_out, int write_logits) {
    const int t = blockIdx.x;
    const int warp = threadIdx.x >> 5;
    const int lane = threadIdx.x & 31;
    __shared__ float slog[NEXP];
    const float* xr = x + (size_t)t * HID;
    const float* wr = Wr + (size_t)warp * HID;
    float s = 0.0f;
    #pragma unroll 4
    for (int i = lane; i < HID; i += 32) s += xr[i] * wr[i];
    #pragma unroll
    for (int o = 16; o > 0; o >>= 1) s += __shfl_xor_sync(0xffffffffu, s, o);
    if (lane == 0) slog[warp] = s;
    __syncthreads();
    if (write_logits && threadIdx.x < NEXP)
        logits_out[t * NEXP + threadIdx.x] = slog[threadIdx.x];
    if (threadIdx.x == 0) {
        float v0 = -1e30f; int i0 = 0;
        #pragma unroll
        for (int i = 0; i < NEXP; i++) if (slog[i] > v0) { v0 = slog[i]; i0 = i; }
        float v1 = -1e30f; int i1 = 0;
        #pragma unroll
        for (int i = 0; i < NEXP; i++)
            if (i != i0 && slog[i] > v1) { v1 = slog[i]; i1 = i; }
        float ex = expf(v1 - v0);
        float inv = 1.0f / (1.0f + ex);
        g_tidx[2 * t] = i0; g_tidx[2 * t + 1] = i1;
        g_tw[2 * t] = inv;  g_tw[2 * t + 1] = ex * inv;
        atomicAdd(&g_cnt[i0], 1);
        atomicAdd(&g_cnt[i1], 1);
    }
}

__global__ void offsets_kernel() {
    if (threadIdx.x == 0) {
        int o = 0;
        #pragma unroll
        for (int e = 0; e < NEXP; e++) { g_off[e] = o; o += g_cnt[e]; }
    }
}

__global__ void scatter_kernel(int T) {
    int t = blockIdx.x * blockDim.x + threadIdx.x;
    if (t >= T) return;
    #pragma unroll
    for (int j = 0; j < 2; j++) {
        int e = g_tidx[2 * t + j];
        int p = atomicAdd(&g_fill[e], 1);
        int slot = g_off[e] + p;
        g_perm[slot] = t;
        g_w[slot] = g_tw[2 * t + j];
        g_slot_of[2 * t + j] = slot;
    }
}

// fused fp32 -> (bf16 hi, bf16 lo) split over x, Wg, Wu, Wd
__device__ __forceinline__ void split4_store(const float4 v, u32* dh, u32* dl, int i) {
    __nv_bfloat162 A = __floats2bfloat162_rn(v.x, v.y);
    __nv_bfloat162 B = __floats2bfloat162_rn(v.z, v.w);
    __nv_bfloat162 Ar = __floats2bfloat162_rn(v.x - __low2float(A), v.y - __high2float(A));
    __nv_bfloat162 Br = __floats2bfloat162_rn(v.z - __low2float(B), v.w - __high2float(B));
    ((uint2*)dh)[i] = make_uint2(*(u32*)&A, *(u32*)&B);
    ((uint2*)dl)[i] = make_uint2(*(u32*)&Ar, *(u32*)&Br);
}

__global__ void split_all_kernel(const float* __restrict__ x,
                                 const float* __restrict__ Wg,
                                 const float* __restrict__ Wu,
                                 const float* __restrict__ Wd, int nx, int nw) {
    int i = blockIdx.x * blockDim.x + threadIdx.x;
    if (i < nx) {
        split4_store(((const float4*)x)[i], (u32*)g_Xh, (u32*)g_Xl, i);
    } else if (i < nx + nw) {
        int j = i - nx;
        split4_store(((const float4*)Wg)[j], (u32*)g_Wgh, (u32*)g_Wgl, j);
    } else if (i < nx + 2 * nw) {
        int j = i - nx - nw;
        split4_store(((const float4*)Wu)[j], (u32*)g_Wuh, (u32*)g_Wul, j);
    } else if (i < nx + 3 * nw) {
        int j = i - nx - 2 * nw;
        split4_store(((const float4*)Wd)[j], (u32*)g_Wdh, (u32*)g_Wdl, j);
    }
}

// ---- GEMM 1: gate+up. CTA: 128 slots x 64 inter cols (g & u), K=2048 ------------
__global__ __launch_bounds__(256, 2) void gateup_mma_kernel() {
    const int e   = blockIdx.z;
    const int cnt = g_cnt[e];
    const int m0  = blockIdx.y * 128;
    if (m0 >= cnt) return;
    const int rows = min(cnt - m0, 128);
    const int base = g_off[e] + m0;
    const int n0   = blockIdx.x * 64;

    extern __shared__ char dsm[];
    const u32 sm0 = smem_u32(dsm);

    const int tid  = threadIdx.x;
    const int lane = tid & 31;
    const int wid  = tid >> 5;
    const int wm   = wid >> 2;          // 0..1 -> 64-row half
    const int wn   = wid & 3;           // 0..3 -> 16 inter cols

    // ---- loader: thread owns 2 full 64B rows of one matrix (v) ----
    const int u = tid & 63;
    const int v = tid >> 6;             // 0:Ah 1:Al 2:Bh 3:Bl
    const __nv_bfloat16 *p0, *p1;
    if (v < 2) {
        const int ra = min(u, rows - 1);
        const int rb = min(u + 64, rows - 1);
        const __nv_bfloat16* Xs = v ? g_Xl : g_Xh;
        p0 = Xs + (size_t)g_perm[base + ra] * HID;
        p1 = Xs + (size_t)g_perm[base + rb] * HID;
    } else {
        // B rows: 0..63 = Wg[n0+u], 64..127 = Wu[n0+u]
        const size_t wrow = ((size_t)e * INTER + n0 + u) * HID;
        p0 = (v == 2 ? g_Wgh : g_Wgl) + wrow;
        p1 = (v == 2 ? g_Wuh : g_Wul) + wrow;
    }
    const u32 offv = (v == 0) ? OFF_AH : (v == 1) ? OFF_AL : (v == 2) ? OFF_BH : OFF_BL;
    const u32 d0 = offv + (u32)u * PITCH;
    const u32 d1 = offv + (u32)(u + 64) * PITCH;

    // ---- ldmatrix bases ----
    const u32 a_off = (u32)((wm * 64 + (lane & 7) + ((lane >> 3) & 1) * 8) * PITCH
                    + (lane >> 4) * 16);
    const u32 bg_off = (u32)((wn * 16 + (lane & 7) + (lane >> 4) * 8) * PITCH
                    + ((lane >> 3) & 1) * 16);
    const u32 bu_off = bg_off + 64 * PITCH;

    float accG[4][2][4], accU[4][2][4];
    #pragma unroll
    for (int i = 0; i < 4; i++)
        #pragma unroll
        for (int j = 0; j < 2; j++)
            #pragma unroll
            for (int k = 0; k < 4; k++) { accG[i][j][k] = 0.0f; accU[i][j][k] = 0.0f; }

    const int KT = HID / 32;            // 64

    // prologue: stage 0
    {
        #pragma unroll
        for (int c = 0; c < 4; c++) {
            cpa16(sm0 + d0 + c * 16, p0 + c * 8);
            cpa16(sm0 + d1 + c * 16, p1 + c * 8);
        }
        CPA_COMMIT();
    }

    #pragma unroll 1
    for (int kt = 0; kt < KT; kt++) {
        CPA_WAIT0();
        __syncthreads();
        if (kt + 1 < KT) {
            const u32 sb = sm0 + (u32)((kt + 1) & 1) * STAGE_BYTES;
            const size_t ko = (size_t)(kt + 1) * 32;
            #pragma unroll
            for (int c = 0; c < 4; c++) {
                cpa16(sb + d0 + c * 16, p0 + ko + c * 8);
                cpa16(sb + d1 + c * 16, p1 + ko + c * 8);
            }
            CPA_COMMIT();
        }
        const u32 sb = sm0 + (u32)(kt & 1) * STAGE_BYTES;
        #pragma unroll
        for (int ks = 0; ks < 2; ks++) {
            u32 ah[4][4], al[4][4], bgh[4], bgl[4], buh[4], bul[4];
            #pragma unroll
            for (int mi = 0; mi < 4; mi++) {
                ldsm4(ah[mi], sb + OFF_AH + a_off + (u32)(mi * 16 * PITCH) + (u32)(ks * 32));
                ldsm4(al[mi], sb + OFF_AL + a_off + (u32)(mi * 16 * PITCH) + (u32)(ks * 32));
            }
            ldsm4(bgh, sb + OFF_BH + bg_off + (u32)(ks * 32));
            ldsm4(bgl, sb + OFF_BL + bg_off + (u32)(ks * 32));
            ldsm4(buh, sb + OFF_BH + bu_off + (u32)(ks * 32));
            ldsm4(bul, sb + OFF_BL + bu_off + (u32)(ks * 32));
            #pragma unroll
            for (int mi = 0; mi < 4; mi++) {
                #pragma unroll
                for (int ni = 0; ni < 2; ni++) {
                    const int s = ni * 2;
                    mma16816(accG[mi][ni], ah[mi], bgh[s], bgh[s + 1]);
                    mma16816(accG[mi][ni], ah[mi], bgl[s], bgl[s + 1]);
                    mma16816(accG[mi][ni], al[mi], bgh[s], bgh[s + 1]);
                    mma16816(accU[mi][ni], ah[mi], buh[s], buh[s + 1]);
                    mma16816(accU[mi][ni], ah[mi], bul[s], bul[s + 1]);
                    mma16816(accU[mi][ni], al[mi], buh[s], buh[s + 1]);
                }
            }
        }
    }
    __syncthreads();

    // ---- epilogue: exchange via smem (128 x 132 f32), silu(g)*u, split hi/lo ----
    float* S = (float*)dsm;
    #pragma unroll
    for (int mi = 0; mi < 4; mi++) {
        const int rr = wm * 64 + mi * 16 + (lane >> 2);
        #pragma unroll
        for (int ni = 0; ni < 2; ni++) {
            const int cg = wn * 16 + ni * 8 + 2 * (lane & 3);
            *(float2*)(S + (size_t)rr * 132 + cg) =
                make_float2(accG[mi][ni][0], accG[mi][ni][1]);
            *(float2*)(S + (size_t)(rr + 8) * 132 + cg) =
                make_float2(accG[mi][ni][2], accG[mi][ni][3]);
            *(float2*)(S + (size_t)rr * 132 + 64 + cg) =
                make_float2(accU[mi][ni][0], accU[mi][ni][1]);
            *(float2*)(S + (size_t)(rr + 8) * 132 + 64 + cg) =
                make_float2(accU[mi][ni][2], accU[mi][ni][3]);
        }
    }
    __syncthreads();
    {
        const int row  = tid >> 1;
        const int half = (tid & 1) * 32;
        if (row < rows) {
            u32 ph[16], pl[16];
            #pragma unroll
            for (int p = 0; p < 16; p++) {
                float g0 = S[(size_t)row * 132 + half + 2 * p];
                float g1 = S[(size_t)row * 132 + half + 2 * p + 1];
                float u0 = S[(size_t)row * 132 + 64 + half + 2 * p];
                float u1 = S[(size_t)row * 132 + 64 + half + 2 * p + 1];
                float h0 = (g0 / (1.0f + expf(-g0))) * u0;
                float h1 = (g1 / (1.0f + expf(-g1))) * u1;
                __nv_bfloat162 A = __floats2bfloat162_rn(h0, h1);
                __nv_bfloat162 B = __floats2bfloat162_rn(h0 - __low2float(A), h1 - __high2float(A));
                ph[p] = *(u32*)&A;
                pl[p] = *(u32*)&B;
            }
            u32* dh = (u32*)(g_Hh + (size_t)(base + row) * INTER + n0 + half);
            u32* dl = (u32*)(g_Hl + (size_t)(base + row) * INTER + n0 + half);
            #pragma unroll
            for (int q = 0; q < 4; q++) {
                ((uint4*)dh)[q] = make_uint4(ph[4*q], ph[4*q+1], ph[4*q+2], ph[4*q+3]);
                ((uint4*)dl)[q] = make_uint4(pl[4*q], pl[4*q+1], pl[4*q+2], pl[4*q+3]);
            }
        }
    }
}

// ---- GEMM 2: down. CTA: 128 slots x 128 hid, K=1024 ------------------------------
__global__ __launch_bounds__(256, 2) void down_mma_kernel() {
    const int e   = blockIdx.z;
    const int cnt = g_cnt[e];
    const int m0  = blockIdx.y * 128;
    if (m0 >= cnt) return;
    const int rows = min(cnt - m0, 128);
    const int base = g_off[e] + m0;
    const int n0   = blockIdx.x * 128;

    extern __shared__ char dsm[];
    const u32 sm0 = smem_u32(dsm);

    const int tid  = threadIdx.x;
    const int lane = tid & 31;
    const int wid  = tid >> 5;
    const int wm   = wid >> 2;
    const int wn   = wid & 3;           // 0..3 -> 32 hid cols

    const int u = tid & 63;
    const int v = tid >> 6;
    const __nv_bfloat16 *p0, *p1;
    if (v < 2) {
        const int ra = min(u, rows - 1);
        const int rb = min(u + 64, rows - 1);
        const __nv_bfloat16* Hs = v ? g_Hl : g_Hh;
        p0 = Hs + (size_t)(base + ra) * INTER;
        p1 = Hs + (size_t)(base + rb) * INTER;
    } else {
        const __nv_bfloat16* Ws = (v == 2) ? g_Wdh : g_Wdl;
        p0 = Ws + ((size_t)e * HID + n0 + u) * INTER;
        p1 = Ws + ((size_t)e * HID + n0 + u + 64) * INTER;
    }
    const u32 offv = (v == 0) ? OFF_AH : (v == 1) ? OFF_AL : (v == 2) ? OFF_BH : OFF_BL;
    const u32 d0 = offv + (u32)u * PITCH;
    const u32 d1 = offv + (u32)(u + 64) * PITCH;

    const u32 a_off = (u32)((wm * 64 + (lane & 7) + ((lane >> 3) & 1) * 8) * PITCH
                    + (lane >> 4) * 16);
    const u32 b_off = (u32)((wn * 32 + (lane & 7) + (lane >> 4) * 8) * PITCH
                    + ((lane >> 3) & 1) * 16);

    float acc[4][4][4];
    #pragma unroll
    for (int i = 0; i < 4; i++)
        #pragma unroll
        for (int j = 0; j < 4; j++)
            #pragma unroll
            for (int k = 0; k < 4; k++) acc[i][j][k] = 0.0f;

    const int KT = INTER / 32;          // 32

    {
        #pragma unroll
        for (int c = 0; c < 4; c++) {
            cpa16(sm0 + d0 + c * 16, p0 + c * 8);
            cpa16(sm0 + d1 + c * 16, p1 + c * 8);
        }
        CPA_COMMIT();
    }

    #pragma unroll 1
    for (int kt = 0; kt < KT; kt++) {
        CPA_WAIT0();
        __syncthreads();
        if (kt + 1 < KT) {
            const u32 sb = sm0 + (u32)((kt + 1) & 1) * STAGE_BYTES;
            const size_t ko = (size_t)(kt + 1) * 32;
            #pragma unroll
            for (int c = 0; c < 4; c++) {
                cpa16(sb + d0 + c * 16, p0 + ko + c * 8);
                cpa16(sb + d1 + c * 16, p1 + ko + c * 8);
            }
            CPA_COMMIT();
        }
        const u32 sb = sm0 + (u32)(kt & 1) * STAGE_BYTES;
        #pragma unroll
        for (int ks = 0; ks < 2; ks++) {
            u32 ah[4][4], al[4][4], bh[2][4], bl[2][4];
            #pragma unroll
            for (int mi = 0; mi < 4; mi++) {
                ldsm4(ah[mi], sb + OFF_AH + a_off + (u32)(mi * 16 * PITCH) + (u32)(ks * 32));
                ldsm4(al[mi], sb + OFF_AL + a_off + (u32)(mi * 16 * PITCH) + (u32)(ks * 32));
            }
            #pragma unroll
            for (int ng = 0; ng < 2; ng++) {
                ldsm4(bh[ng], sb + OFF_BH + b_off + (u32)(ng * 16 * PITCH) + (u32)(ks * 32));
                ldsm4(bl[ng], sb + OFF_BL + b_off + (u32)(ng * 16 * PITCH) + (u32)(ks * 32));
            }
            #pragma unroll
            for (int mi = 0; mi < 4; mi++) {
                #pragma unroll
                for (int ni = 0; ni < 4; ni++) {
                    const int q = ni >> 1, s = (ni & 1) * 2;
                    mma16816(acc[mi][ni], ah[mi], bh[q][s], bh[q][s + 1]);
                    mma16816(acc[mi][ni], ah[mi], bl[q][s], bl[q][s + 1]);
                    mma16816(acc[mi][ni], al[mi], bh[q][s], bh[q][s + 1]);
                }
            }
        }
    }

    // ---- epilogue: scale by routing weight, store f32 ----
    #pragma unroll
    for (int mi = 0; mi < 4; mi++) {
        const int r0o = wm * 64 + mi * 16 + (lane >> 2);
        const int r1o = r0o + 8;
        #pragma unroll
        for (int ni = 0; ni < 4; ni++) {
            const int cc = n0 + wn * 32 + ni * 8 + 2 * (lane & 3);
            if (r0o < rows) {
                const float w0 = g_w[base + r0o];
                *(float2*)(g_y + (size_t)(base + r0o) * HID + cc) =
                    make_float2(w0 * acc[mi][ni][0], w0 * acc[mi][ni][1]);
            }
            if (r1o < rows) {
                const float w1 = g_w[base + r1o];
                *(float2*)(g_y + (size_t)(base + r1o) * HID + cc) =
                    make_float2(w1 * acc[mi][ni][2], w1 * acc[mi][ni][3]);
            }
        }
    }
}

// ---- combine: out[t] = y[slot0] + y[slot1] ----------------------------------------
__global__ void combine_kernel(float* __restrict__ out, int T) {
    const int gid = blockIdx.x * blockDim.x + threadIdx.x;
    const int per_tok = HID / 4;
    if (gid >= T * per_tok) return;
    const int t = gid / per_tok;
    const int c = gid - t * per_tok;
    const int s0 = g_slot_of[2 * t];
    const int s1 = g_slot_of[2 * t + 1];
    float4 a = ((const float4*)(g_y + (size_t)s0 * HID))[c];
    float4 b = ((const float4*)(g_y + (size_t)s1 * HID))[c];
    ((float4*)(out + (size_t)t * HID))[c] =
        make_float4(a.x + b.x, a.y + b.y, a.z + b.z, a.w + b.w);
}

// ---- launch -------------------------------------------------------------------------
extern "C" void kernel_launch(void* const* d_in, const int* in_sizes, int n_in,
                              void* d_out, int out_size) {
    if (n_in < 5) return;
    const float* x  = (const float*)d_in[0];
    const float* Wr = (const float*)d_in[1];
    const float* Wg = (const float*)d_in[2];
    const float* Wu = (const float*)d_in[3];
    const float* Wd = (const float*)d_in[4];
    float* out = (float*)d_out;

    int T = in_sizes[0] / HID;
    if (T > MAXT) T = MAXT;

    cudaFuncSetAttribute(gateup_mma_kernel, cudaFuncAttributeMaxDynamicSharedMemorySize, SMEM_DYN);
    cudaFuncSetAttribute(down_mma_kernel,   cudaFuncAttributeMaxDynamicSharedMemorySize, SMEM_DYN);

    const int write_logits = (out_size >= T * HID + T * NEXP);
    float* logits = out + (size_t)T * HID;

    zero_counters_kernel<<<1, 32>>>();
    router_kernel<<<T, 256>>>(x, Wr, logits, write_logits);
    offsets_kernel<<<1, 32>>>();
    scatter_kernel<<<(T + 255) / 256, 256>>>(T);

    const int nx = T * HID / 4;
    const int nw = NEXP * INTER * HID / 4;
    split_all_kernel<<<(nx + 3 * nw + 255) / 256, 256>>>(x, Wg, Wu, Wd, nx, nw);

    gateup_mma_kernel<<<dim3(INTER / 64, MAXSLOTS / 128, NEXP), 256, SMEM_DYN>>>();
    down_mma_kernel<<<dim3(HID / 128, MAXSLOTS / 128, NEXP), 256, SMEM_DYN>>>();

    combine_kernel<<<(T * (HID / 4) + 255) / 256, 256>>>(out, T);
}